// round 2
// baseline (speedup 1.0000x reference)
#include <cuda_runtime.h>
#include <cstdint>

// Problem constants (fixed by the reference)
#define KFEAT   128      // NUM_FEATURES
#define NTHETA  32       // NUM_THETAS
#define NSTEP   32       // BUMP_STEPS
#define TILE_N  128      // nodes per block tile
#define KC      32       // k-chunk staged in shared
#define NTHREADS 256
#define XPAD    132      // xT row pitch (multiple of 4 for LDS.128)
#define HPITCH  33       // acc/hist pitch to randomize atomic banks

__device__ __forceinline__ float fast_sigmoid(float z) {
    float e = __expf(-z);
    return __fdividef(1.0f, 1.0f + e);
}

__global__ void zero_kernel(float* __restrict__ out, int n) {
    int i = blockIdx.x * blockDim.x + threadIdx.x;
    if (i < n) out[i] = 0.0f;
}

union F4U { float4 v; float f[4]; };

__global__ void __launch_bounds__(NTHREADS)
ect_fused_kernel(const float* __restrict__ x,
                 const void*  __restrict__ batch_raw,
                 const float* __restrict__ v,
                 float* __restrict__ out,
                 int n_nodes)
{
    __shared__ float xT[KC * XPAD];                 // transposed x chunk  (16.9 KB)
    __shared__ float vs[NTHETA * KFEAT];            // full v, [t][k]      (16 KB)
    __shared__ float accs[NSTEP * HPITCH];          // sigmoid partials    (4.2 KB)
    __shared__ int   hist[(NSTEP + 1) * HPITCH];    // step histogram      (4.4 KB)
    __shared__ int   bsh[TILE_N];
    __shared__ int   s_segend;

    const int tid = threadIdx.x;
    const int ng  = tid & 31;     // node group (4 nodes each) — lane id
    const int tg  = tid >> 5;     // theta group (4 thetas each) — warp id
    const int tile_base = blockIdx.x * TILE_N;
    const int valid_n = min(TILE_N, n_nodes - tile_base);

    // Detect batch dtype: int64 (JAX x64 on) vs int32 (default JAX).
    // word[N-1]: int64 -> high half of elem (N-1)/2 == 0; int32 -> last sorted label (>0).
    const unsigned* bw = (const unsigned*)batch_raw;
    const bool is64 = (bw[n_nodes - 1] == 0u);

    // Stage v (contiguous float4 copy, layout [t][k] kept as-is)
    {
        const float4* v4 = (const float4*)v;
        float4* vs4 = (float4*)vs;
        #pragma unroll
        for (int j = 0; j < (NTHETA * KFEAT / 4) / NTHREADS; ++j)
            vs4[j * NTHREADS + tid] = v4[j * NTHREADS + tid];
    }
    // Stage batch labels for this tile
    if (tid < TILE_N) {
        int n = tile_base + tid;
        int b = 0x7fffffff;
        if (n < n_nodes)
            b = is64 ? (int)((const long long*)batch_raw)[n]
                     : ((const int*)batch_raw)[n];
        bsh[tid] = b;
    }

    // ---- GEMM: nh tile in registers, 4 nodes x 4 thetas per thread ----
    float acc[4][4];
    #pragma unroll
    for (int i = 0; i < 4; ++i)
        #pragma unroll
        for (int j = 0; j < 4; ++j) acc[i][j] = 0.0f;

    #pragma unroll 1
    for (int kc = 0; kc < KFEAT / KC; ++kc) {
        __syncthreads();
        // Stage x chunk transposed: xT[kk][node], coalesced float4 global reads
        #pragma unroll
        for (int it = 0; it < (TILE_N * KC / 4) / NTHREADS; ++it) {
            int idx = it * NTHREADS + tid;
            int r = idx >> 3;          // node row 0..127
            int q = idx & 7;           // float4 within 32-col chunk
            int n = tile_base + r;
            if (n >= n_nodes) n = n_nodes - 1;   // clamp (values unused for invalid nodes)
            float4 xx = *(const float4*)(x + (size_t)n * KFEAT + kc * KC + q * 4);
            xT[(q * 4 + 0) * XPAD + r] = xx.x;
            xT[(q * 4 + 1) * XPAD + r] = xx.y;
            xT[(q * 4 + 2) * XPAD + r] = xx.z;
            xT[(q * 4 + 3) * XPAD + r] = xx.w;
        }
        __syncthreads();
        #pragma unroll
        for (int kk4 = 0; kk4 < KC / 4; ++kk4) {
            F4U vv[4];
            #pragma unroll
            for (int j = 0; j < 4; ++j)
                vv[j].v = *(const float4*)&vs[(4 * tg + j) * KFEAT + kc * KC + kk4 * 4];
            #pragma unroll
            for (int u = 0; u < 4; ++u) {
                float4 xx = *(const float4*)&xT[(kk4 * 4 + u) * XPAD + 4 * ng];
                #pragma unroll
                for (int j = 0; j < 4; ++j) {
                    float vb = vv[j].f[u];
                    acc[0][j] = fmaf(xx.x, vb, acc[0][j]);
                    acc[1][j] = fmaf(xx.y, vb, acc[1][j]);
                    acc[2][j] = fmaf(xx.z, vb, acc[2][j]);
                    acc[3][j] = fmaf(xx.w, vb, acc[3][j]);
                }
            }
        }
    }

    // ---- Epilogue: step-function decomposition + per-graph-segment reduction ----
    const float Rr       = 1.1f;
    const float STEP     = 2.2f / 31.0f;
    const float INV_STEP = 31.0f / 2.2f;
    const float SCALE    = 100.0f;
    const float Wb       = 0.2f * INV_STEP;   // half-window in s-units (z threshold = 20)

    int seg_start = 0;
    #pragma unroll 1
    while (seg_start < valid_n) {
        __syncthreads();                      // previous flush done before re-zeroing
        const int g = bsh[seg_start];
        if (tid == 0) s_segend = valid_n;
        for (int i = tid; i < NSTEP * HPITCH; i += NTHREADS) accs[i] = 0.0f;
        for (int i = tid; i < (NSTEP + 1) * HPITCH; i += NTHREADS) hist[i] = 0;
        __syncthreads();
        if (tid < valid_n && tid > seg_start && bsh[tid] != g)
            atomicMin(&s_segend, tid);        // sorted batch -> first mismatch = seg end
        __syncthreads();
        const int seg_end = s_segend;

        #pragma unroll
        for (int i = 0; i < 4; ++i) {
            int n_local = 4 * ng + i;
            if (n_local >= seg_start && n_local < seg_end) {
                #pragma unroll
                for (int j = 0; j < 4; ++j) {
                    int t = 4 * tg + j;
                    float nh = acc[i][j];
                    float a  = (nh + Rr) * INV_STEP;       // crossing position in s-units
                    int idx_hi = (int)ceilf(a + Wb);       // first s contributing exactly 1
                    idx_hi = max(0, min(NSTEP, idx_hi));
                    atomicAdd(&hist[idx_hi * HPITCH + t], 1);
                    int s0 = max(0, (int)ceilf(a - Wb));
                    int s1 = min(idx_hi, NSTEP);
                    for (int s = s0; s < s1; ++s) {        // <=7 transition samples
                        float lin = fmaf((float)s, STEP, -Rr);
                        float z = SCALE * (lin - nh);
                        atomicAdd(&accs[s * HPITCH + t], fast_sigmoid(z));
                    }
                }
            }
        }
        __syncthreads();

        if (tid < NTHETA) {                   // suffix-sum + flush: one thread per theta
            int t = tid;
            float run = 0.0f;
            float cnt = (float)(seg_end - seg_start);
            float* og = out + (size_t)g * (NSTEP * NTHETA);
            #pragma unroll 1
            for (int s = 0; s < NSTEP; ++s) {
                run += (float)hist[s * HPITCH + t];
                float lin = fmaf((float)s, STEP, -Rr);
                float zc  = SCALE * (lin - Rr);
                float cs  = (zc > -25.0f) ? fast_sigmoid(zc) : 0.0f;  // pad term c[s]
                float val = accs[s * HPITCH + t] + run - cnt * cs;
                atomicAdd(&og[s * NTHETA + t], val);
            }
        }
        seg_start = seg_end;
    }
}

extern "C" void kernel_launch(void* const* d_in, const int* in_sizes, int n_in,
                              void* d_out, int out_size) {
    // Identify inputs by element count (robust to num_graphs scalar placement):
    // x = largest; v = 32*128 = 4096; batch = n_nodes = x_elems/128.
    int xi = 0; long long best = -1;
    for (int i = 0; i < n_in; ++i)
        if ((long long)in_sizes[i] > best) { best = in_sizes[i]; xi = i; }
    const float* x = (const float*)d_in[xi];
    int n_nodes = (int)(best / KFEAT);
    const void* batch = nullptr;
    const float* v = nullptr;
    for (int i = 0; i < n_in; ++i) {
        if (i == xi) continue;
        if (in_sizes[i] == NTHETA * KFEAT) v = (const float*)d_in[i];
        else if (in_sizes[i] == n_nodes)   batch = d_in[i];
    }
    float* out = (float*)d_out;

    zero_kernel<<<(out_size + 255) / 256, 256>>>(out, out_size);
    int tiles = (n_nodes + TILE_N - 1) / TILE_N;
    ect_fused_kernel<<<tiles, NTHREADS>>>(x, batch, v, out, n_nodes);
}

// round 3
// speedup vs baseline: 1.3059x; 1.3059x over previous
#include <cuda_runtime.h>
#include <cstdint>

// Problem constants (fixed by the reference)
#define KFEAT   128      // NUM_FEATURES
#define NTHETA  32       // NUM_THETAS
#define NSTEP   32       // BUMP_STEPS
#define TILE_N  128      // nodes per block tile
#define KC      32       // k-chunk staged in shared
#define NTHREADS 256
#define XPAD    132      // xT row pitch (multiple of 4 for LDS.128)
#define HP      33       // acc/hist pitch to spread banks

__device__ __forceinline__ float fast_sigmoid(float z) {
    float e = __expf(-z);
    return __fdividef(1.0f, 1.0f + e);
}

__global__ void zero_kernel(float* __restrict__ out, int n) {
    int i = blockIdx.x * blockDim.x + threadIdx.x;
    if (i < n) out[i] = 0.0f;
}

union F4U { float4 v; float f[4]; };

__global__ void __launch_bounds__(NTHREADS, 2)
ect_fused_kernel(const float* __restrict__ x,
                 const void*  __restrict__ batch_raw,
                 const float* __restrict__ v,
                 float* __restrict__ out,
                 int n_nodes)
{
    __shared__ float xT[KC * XPAD];                 // transposed x chunk
    __shared__ float vs[NTHETA * KFEAT];            // full v, [t][k]
    __shared__ float accs[NSTEP * HP];              // transition sigmoid partials
    __shared__ int   hist[NSTEP * HP];              // mid-band step histogram (bins 1..31)
    __shared__ int   base_sh[NTHETA];               // "contributes to all s" counts
    __shared__ int   bsh[TILE_N];
    __shared__ int   s_segend;

    const int tid = threadIdx.x;
    const int ng  = tid & 31;     // lane: node group (4 nodes each)
    const int tg  = tid >> 5;     // warp: theta group (4 thetas each) -> warps own disjoint t
    const int tile_base = blockIdx.x * TILE_N;
    const int valid_n = min(TILE_N, n_nodes - tile_base);

    // Detect batch dtype: int64 (JAX x64 on) vs int32 (default).
    const unsigned* bw = (const unsigned*)batch_raw;
    const bool is64 = (bw[n_nodes - 1] == 0u);

    // Stage v
    {
        const float4* v4 = (const float4*)v;
        float4* vs4 = (float4*)vs;
        #pragma unroll
        for (int j = 0; j < (NTHETA * KFEAT / 4) / NTHREADS; ++j)
            vs4[j * NTHREADS + tid] = v4[j * NTHREADS + tid];
    }
    // Stage batch labels for this tile
    if (tid < TILE_N) {
        int n = tile_base + tid;
        int b = 0x7fffffff;
        if (n < n_nodes)
            b = is64 ? (int)((const long long*)batch_raw)[n]
                     : ((const int*)batch_raw)[n];
        bsh[tid] = b;
    }

    // ---- GEMM: nh tile in registers, 4 nodes x 4 thetas per thread ----
    float acc[4][4];
    #pragma unroll
    for (int i = 0; i < 4; ++i)
        #pragma unroll
        for (int j = 0; j < 4; ++j) acc[i][j] = 0.0f;

    #pragma unroll 1
    for (int kc = 0; kc < KFEAT / KC; ++kc) {
        __syncthreads();
        #pragma unroll
        for (int it = 0; it < (TILE_N * KC / 4) / NTHREADS; ++it) {
            int idx = it * NTHREADS + tid;
            int r = idx >> 3;          // node row 0..127
            int q = idx & 7;           // float4 within 32-col chunk
            int n = tile_base + r;
            if (n >= n_nodes) n = n_nodes - 1;
            float4 xx = *(const float4*)(x + (size_t)n * KFEAT + kc * KC + q * 4);
            xT[(q * 4 + 0) * XPAD + r] = xx.x;
            xT[(q * 4 + 1) * XPAD + r] = xx.y;
            xT[(q * 4 + 2) * XPAD + r] = xx.z;
            xT[(q * 4 + 3) * XPAD + r] = xx.w;
        }
        __syncthreads();
        #pragma unroll
        for (int kk4 = 0; kk4 < KC / 4; ++kk4) {
            F4U vv[4];
            #pragma unroll
            for (int j = 0; j < 4; ++j)
                vv[j].v = *(const float4*)&vs[(4 * tg + j) * KFEAT + kc * KC + kk4 * 4];
            #pragma unroll
            for (int u = 0; u < 4; ++u) {
                float4 xx = *(const float4*)&xT[(kk4 * 4 + u) * XPAD + 4 * ng];
                #pragma unroll
                for (int j = 0; j < 4; ++j) {
                    float vb = vv[j].f[u];
                    acc[0][j] = fmaf(xx.x, vb, acc[0][j]);
                    acc[1][j] = fmaf(xx.y, vb, acc[1][j]);
                    acc[2][j] = fmaf(xx.z, vb, acc[2][j]);
                    acc[3][j] = fmaf(xx.w, vb, acc[3][j]);
                }
            }
        }
    }

    // ---- Epilogue: step decomposition, atomic-minimized ----
    const float Rr       = 1.1f;
    const float STEP     = 2.2f / 31.0f;
    const float INV_STEP = 31.0f / 2.2f;
    const float SCALE    = 100.0f;
    const float Wb       = 0.08f * INV_STEP;   // z threshold 8 -> snap err e^-8

    int seg_start = 0;
    #pragma unroll 1
    while (seg_start < valid_n) {
        __syncthreads();                      // previous flush done before re-zeroing
        const int g = bsh[seg_start];
        if (tid == 0) s_segend = valid_n;
        for (int i2 = tid; i2 < NSTEP * HP; i2 += NTHREADS) { accs[i2] = 0.0f; hist[i2] = 0; }
        if (tid < NTHETA) base_sh[tid] = 0;
        __syncthreads();
        if (tid < valid_n && tid > seg_start && bsh[tid] != g)
            atomicMin(&s_segend, tid);        // sorted batch -> first mismatch = seg end
        __syncthreads();
        const int seg_end = s_segend;

        int basec0 = 0, basec1 = 0, basec2 = 0, basec3 = 0;

        #pragma unroll
        for (int i = 0; i < 4; ++i) {
            const int n_local = 4 * ng + i;
            const bool valid = (n_local >= seg_start) && (n_local < seg_end);
            #pragma unroll
            for (int j = 0; j < 4; ++j) {
                float nh = acc[i][j];
                float a  = (nh + Rr) * INV_STEP;      // crossing position in s-units
                int ihi  = (int)ceilf(a + Wb);        // first s with full contribution
                ihi = max(0, min(NSTEP, ihi));
                // Aggregate the dominant ihi==0 bin (contributes 1 to every s)
                // via ballot -> warp-uniform register. No atomic, no divergence.
                unsigned bal = __ballot_sync(0xffffffffu, valid && (ihi == 0));
                int bp = __popc(bal);
                if (j == 0) basec0 += bp;
                else if (j == 1) basec1 += bp;
                else if (j == 2) basec2 += bp;
                else basec3 += bp;

                if (valid) {
                    int t = 4 * tg + j;
                    if (ihi >= 1 && ihi <= 31)        // mid-band only (~31% of nodes)
                        atomicAdd(&hist[ihi * HP + t], 1);
                    int s0 = max(0, (int)ceilf(a - Wb));
                    int s1 = min(ihi, NSTEP);
                    #pragma unroll 1
                    for (int s = s0; s < s1; ++s) {   // <=3-4 transition samples
                        float lin = fmaf((float)s, STEP, -Rr);
                        atomicAdd(&accs[s * HP + t], fast_sigmoid(SCALE * (lin - nh)));
                    }
                }
            }
        }
        // Flush warp-uniform base counts: lanes 0..3 each post one value.
        if (ng == 0) atomicAdd(&base_sh[4 * tg + 0], basec0);
        if (ng == 1) atomicAdd(&base_sh[4 * tg + 1], basec1);
        if (ng == 2) atomicAdd(&base_sh[4 * tg + 2], basec2);
        if (ng == 3) atomicAdd(&base_sh[4 * tg + 3], basec3);
        __syncthreads();

        if (tid < NTHETA) {                   // suffix-sum + flush: one thread per theta
            int t = tid;
            float run = (float)base_sh[t];    // ihi==0 nodes count at every s
            float cnt = (float)(seg_end - seg_start);
            float* og = out + (size_t)g * (NSTEP * NTHETA);
            #pragma unroll 1
            for (int s = 0; s < NSTEP; ++s) {
                run += (float)hist[s * HP + t];
                float lin = fmaf((float)s, STEP, -Rr);
                float zc  = SCALE * (lin - Rr);
                float cs  = (zc > -25.0f) ? fast_sigmoid(zc) : 0.0f;  // pad term c[s]
                float val = accs[s * HP + t] + run - cnt * cs;
                atomicAdd(&og[s * NTHETA + t], val);
            }
        }
        seg_start = seg_end;
    }
}

extern "C" void kernel_launch(void* const* d_in, const int* in_sizes, int n_in,
                              void* d_out, int out_size) {
    // Identify inputs by element count: x = largest; v = 32*128; batch = n_nodes.
    int xi = 0; long long best = -1;
    for (int i = 0; i < n_in; ++i)
        if ((long long)in_sizes[i] > best) { best = in_sizes[i]; xi = i; }
    const float* x = (const float*)d_in[xi];
    int n_nodes = (int)(best / KFEAT);
    const void* batch = nullptr;
    const float* v = nullptr;
    for (int i = 0; i < n_in; ++i) {
        if (i == xi) continue;
        if (in_sizes[i] == NTHETA * KFEAT) v = (const float*)d_in[i];
        else if (in_sizes[i] == n_nodes)   batch = d_in[i];
    }
    float* out = (float*)d_out;

    zero_kernel<<<(out_size + 255) / 256, 256>>>(out, out_size);
    int tiles = (n_nodes + TILE_N - 1) / TILE_N;
    ect_fused_kernel<<<tiles, NTHREADS>>>(x, batch, v, out, n_nodes);
}